// round 10
// baseline (speedup 1.0000x reference)
#include <cuda_runtime.h>
#include <math.h>

// ChamferLoss: B=4, N=8192, K=8 nearest neighbors, L2 norm.
// loss = mean over all (query, knn) exact distances, both directions.
//
// R10: EXACT windowed sweep. Sort each point set by x (bitonic on 19-bit
//      orderable-float keys, materialize sorted SoA). Each warp owns 32
//      consecutive x-sorted queries and expands a candidate window outward,
//      stopping when the boundary x is provably outside warp-max kth dist
//      (+ eps for key truncation). ~6-8x less pair work than brute force.

namespace {
constexpr int B_      = 4;
constexpr int N_      = 8192;
constexpr int KNN     = 8;
constexpr int NSETS   = B_ * 2;                 // b*2+s: s=0 pred(src+flow), s=1 tgt
constexpr int THREADS = 128;
constexpr int WPB     = THREADS / 32;           // 4 warps/block
constexpr int QPW     = 32;                     // queries per warp (1 per lane)
constexpr int WARPS_T = NSETS * N_ / QPW;       // 2048 warps total
constexpr int KBLOCKS = WARPS_T / WPB;          // 512 blocks
constexpr int WPD     = N_ / QPW;               // 256 warps per (batch,dir)
constexpr int CHW     = 128;                    // candidates per chunk
constexpr int NCH     = N_ / CHW;               // 64 chunks
constexpr float DELTA = 0.02f;                  // covers 19-bit key truncation (|x|<8)
}

// Scratch (static device globals: no allocation).
__device__ float g_px[NSETS][N_];               // sorted-by-x coordinates, SoA
__device__ float g_py[NSETS][N_];
__device__ float g_pz[NSETS][N_];
__device__ float g_partials[WARPS_T];

__device__ __forceinline__ unsigned ordf(float x) {  // monotone float->uint
    unsigned u = __float_as_uint(x);
    return (u & 0x80000000u) ? ~u : (u | 0x80000000u);
}

// ---------------- sort each set by x (one 1024-thread block per set) -------
__global__ __launch_bounds__(1024)
void sortx_kernel(const float* __restrict__ src,
                  const float* __restrict__ tgt,
                  const float* __restrict__ flow)
{
    __shared__ unsigned sk[N_];                  // 32 KB
    const int set = blockIdx.x;
    const int b   = set >> 1;
    const int s   = set & 1;
    const float* __restrict__ sb = src  + (size_t)b * N_ * 3;
    const float* __restrict__ tb = tgt  + (size_t)b * N_ * 3;
    const float* __restrict__ fb = flow + (size_t)b * N_ * 3;

    for (int i = threadIdx.x; i < N_; i += 1024) {
        const float x = (s == 0) ? (sb[3 * i] + fb[3 * i]) : tb[3 * i];
        sk[i] = (ordf(x) & 0xFFFFE000u) | (unsigned)i;   // 19-bit key | 13-bit idx
    }
    __syncthreads();

    for (int k = 2; k <= N_; k <<= 1) {
        for (int j = k >> 1; j > 0; j >>= 1) {
            for (int t = threadIdx.x; t < N_; t += 1024) {
                const int p = t ^ j;
                if (p > t) {
                    const unsigned a = sk[t], c = sk[p];
                    const bool up = ((t & k) == 0);
                    if ((a > c) == up) { sk[t] = c; sk[p] = a; }
                }
            }
            __syncthreads();
        }
    }

    for (int i = threadIdx.x; i < N_; i += 1024) {
        const int idx = (int)(sk[i] & (unsigned)(N_ - 1));
        float x, y, z;
        if (s == 0) {
            x = sb[3 * idx + 0] + fb[3 * idx + 0];
            y = sb[3 * idx + 1] + fb[3 * idx + 1];
            z = sb[3 * idx + 2] + fb[3 * idx + 2];
        } else {
            x = tb[3 * idx + 0]; y = tb[3 * idx + 1]; z = tb[3 * idx + 2];
        }
        g_px[set][i] = x; g_py[set][i] = y; g_pz[set][i] = z;
    }
}

// ---------------- exact windowed KNN (one warp = 32 sorted queries) --------
__global__ __launch_bounds__(THREADS)
void knn_kernel()
{
    __shared__ __align__(16) float sx[WPB][CHW];
    __shared__ __align__(16) float sy[WPB][CHW];
    __shared__ __align__(16) float sz[WPB][CHW];

    const int tid  = threadIdx.x;
    const int lane = tid & 31;
    const int wib  = tid >> 5;
    const int gw   = blockIdx.x * WPB + wib;     // global warp id
    const int bd   = gw / WPD;                   // b*2 + dir
    const int wq   = gw % WPD;                   // warp's query-slice within set
    const int qset = bd;                         // queries = sorted set bd
    const int cset = bd ^ 1;                     // candidates = the other set
    const int slot = wq * QPW + lane;

    const float qx = g_px[qset][slot];
    const float qy = g_py[qset][slot];
    const float qz = g_pz[qset][slot];

    // warp query x-range (exact values)
    float xqmin = qx, xqmax = qx;
#pragma unroll
    for (int o = 16; o > 0; o >>= 1) {
        xqmin = fminf(xqmin, __shfl_xor_sync(0xffffffffu, xqmin, o));
        xqmax = fmaxf(xqmax, __shfl_xor_sync(0xffffffffu, xqmax, o));
    }

    const float* __restrict__ cx = g_px[cset];
    const float* __restrict__ cy = g_py[cset];
    const float* __restrict__ cz = g_pz[cset];

    float h[KNN];
#pragma unroll
    for (int i = 0; i < KNN; ++i) h[i] = 3.0e38f;
    unsigned tbits = __float_as_uint(3.0e38f);

    // scan one 128-candidate chunk (warp-cooperative smem tile)
    auto scan = [&](int c) {
        const int base = c * CHW;
        const float4 vx = reinterpret_cast<const float4*>(cx + base)[lane];
        const float4 vy = reinterpret_cast<const float4*>(cy + base)[lane];
        const float4 vz = reinterpret_cast<const float4*>(cz + base)[lane];
        __syncwarp();                             // tile free before overwrite
        reinterpret_cast<float4*>(sx[wib])[lane] = vx;
        reinterpret_cast<float4*>(sy[wib])[lane] = vy;
        reinterpret_cast<float4*>(sz[wib])[lane] = vz;
        __syncwarp();
#pragma unroll 4
        for (int j = 0; j < CHW; ++j) {
            const float dx = qx - sx[wib][j];     // broadcast LDS
            const float dy = qy - sy[wib][j];
            const float dz = qz - sz[wib][j];
            const float d2 = fmaf(dx, dx, fmaf(dy, dy, dz * dz));
            const unsigned db = __float_as_uint(d2);   // d2 >= 0: uint cmp == float cmp
            if (__builtin_expect(db < tbits, 0)) {
                float v = d2;
#pragma unroll
                for (int i = KNN - 1; i > 0; --i) {
                    const float hp = h[i - 1];
                    h[i] = fmaxf(hp, v);
                    v    = fminf(hp, v);
                }
                h[0] = v;
                tbits = __float_as_uint(h[KNN - 1]);
            }
        }
    };

    // rank-aligned start chunk, then symmetric expansion with exact bounds
    int c0 = (wq * QPW + QPW / 2) / CHW;
    if (c0 >= NCH) c0 = NCH - 1;
    scan(c0);
    int lo = c0, hi = c0 + 1;

    for (;;) {
        float tmax = h[KNN - 1];
#pragma unroll
        for (int o = 16; o > 0; o >>= 1)
            tmax = fmaxf(tmax, __shfl_xor_sync(0xffffffffu, tmax, o));
        const float td = sqrtf(tmax);

        // boundary reads are warp-uniform addresses -> uniform predicates
        const bool left  = (lo > 0)   && (cx[lo * CHW - 1] > xqmin - td - DELTA);
        const bool right = (hi < NCH) && (cx[hi * CHW]     < xqmax + td + DELTA);
        if (left)  { --lo; scan(lo); }
        if (right) { scan(hi); ++hi; }
        if (!left && !right) break;
    }

    // per-lane sum of 8 exact distances, warp-reduce, one partial per warp
    float s = 0.0f;
#pragma unroll
    for (int i = 0; i < KNN; ++i) s += sqrtf(h[i]);
#pragma unroll
    for (int o = 16; o > 0; o >>= 1)
        s += __shfl_down_sync(0xffffffffu, s, o);
    if (lane == 0) g_partials[gw] = s;
}

// ---------------- final deterministic reduction -----------------------------
__global__ __launch_bounds__(1024)
void reduce_kernel(float* __restrict__ out)
{
    const int t = threadIdx.x;
    float v = g_partials[t] + g_partials[t + 1024];
#pragma unroll
    for (int o = 16; o > 0; o >>= 1)
        v += __shfl_down_sync(0xffffffffu, v, o);

    __shared__ float ws[32];
    if ((t & 31) == 0) ws[t >> 5] = v;
    __syncthreads();
    if (t == 0) {
        float s = 0.0f;
#pragma unroll
        for (int i = 0; i < 32; ++i) s += ws[i];
        out[0] = s * (1.0f / (float)(B_ * N_ * KNN));
    }
}

extern "C" void kernel_launch(void* const* d_in, const int* in_sizes, int n_in,
                              void* d_out, int out_size)
{
    (void)in_sizes; (void)n_in; (void)out_size;
    const float* src  = (const float*)d_in[0];
    const float* tgt  = (const float*)d_in[1];
    const float* flow = (const float*)d_in[2];
    float* out = (float*)d_out;

    sortx_kernel<<<NSETS, 1024>>>(src, tgt, flow);
    knn_kernel<<<KBLOCKS, THREADS>>>();
    reduce_kernel<<<1, 1024>>>(out);
}

// round 11
// speedup vs baseline: 1.0009x; 1.0009x over previous
#include <cuda_runtime.h>
#include <math.h>

// ChamferLoss: B=4, N=8192, K=8 nearest neighbors, L2 norm.
// loss = mean over all (query, knn) exact distances, both directions.
//
// R10: EXACT windowed sweep. Sort each point set by x (bitonic on 19-bit
//      orderable-float keys, materialize sorted SoA). Each warp owns 32
//      consecutive x-sorted queries and expands a candidate window outward,
//      stopping when the boundary x is provably outside warp-max kth dist
//      (+ eps for key truncation). ~6-8x less pair work than brute force.

namespace {
constexpr int B_      = 4;
constexpr int N_      = 8192;
constexpr int KNN     = 8;
constexpr int NSETS   = B_ * 2;                 // b*2+s: s=0 pred(src+flow), s=1 tgt
constexpr int THREADS = 128;
constexpr int WPB     = THREADS / 32;           // 4 warps/block
constexpr int QPW     = 32;                     // queries per warp (1 per lane)
constexpr int WARPS_T = NSETS * N_ / QPW;       // 2048 warps total
constexpr int KBLOCKS = WARPS_T / WPB;          // 512 blocks
constexpr int WPD     = N_ / QPW;               // 256 warps per (batch,dir)
constexpr int CHW     = 128;                    // candidates per chunk
constexpr int NCH     = N_ / CHW;               // 64 chunks
constexpr float DELTA = 0.02f;                  // covers 19-bit key truncation (|x|<8)
}

// Scratch (static device globals: no allocation).
__device__ float g_px[NSETS][N_];               // sorted-by-x coordinates, SoA
__device__ float g_py[NSETS][N_];
__device__ float g_pz[NSETS][N_];
__device__ float g_partials[WARPS_T];

__device__ __forceinline__ unsigned ordf(float x) {  // monotone float->uint
    unsigned u = __float_as_uint(x);
    return (u & 0x80000000u) ? ~u : (u | 0x80000000u);
}

// ---------------- sort each set by x (one 1024-thread block per set) -------
__global__ __launch_bounds__(1024)
void sortx_kernel(const float* __restrict__ src,
                  const float* __restrict__ tgt,
                  const float* __restrict__ flow)
{
    __shared__ unsigned sk[N_];                  // 32 KB
    const int set = blockIdx.x;
    const int b   = set >> 1;
    const int s   = set & 1;
    const float* __restrict__ sb = src  + (size_t)b * N_ * 3;
    const float* __restrict__ tb = tgt  + (size_t)b * N_ * 3;
    const float* __restrict__ fb = flow + (size_t)b * N_ * 3;

    for (int i = threadIdx.x; i < N_; i += 1024) {
        const float x = (s == 0) ? (sb[3 * i] + fb[3 * i]) : tb[3 * i];
        sk[i] = (ordf(x) & 0xFFFFE000u) | (unsigned)i;   // 19-bit key | 13-bit idx
    }
    __syncthreads();

    for (int k = 2; k <= N_; k <<= 1) {
        for (int j = k >> 1; j > 0; j >>= 1) {
            for (int t = threadIdx.x; t < N_; t += 1024) {
                const int p = t ^ j;
                if (p > t) {
                    const unsigned a = sk[t], c = sk[p];
                    const bool up = ((t & k) == 0);
                    if ((a > c) == up) { sk[t] = c; sk[p] = a; }
                }
            }
            __syncthreads();
        }
    }

    for (int i = threadIdx.x; i < N_; i += 1024) {
        const int idx = (int)(sk[i] & (unsigned)(N_ - 1));
        float x, y, z;
        if (s == 0) {
            x = sb[3 * idx + 0] + fb[3 * idx + 0];
            y = sb[3 * idx + 1] + fb[3 * idx + 1];
            z = sb[3 * idx + 2] + fb[3 * idx + 2];
        } else {
            x = tb[3 * idx + 0]; y = tb[3 * idx + 1]; z = tb[3 * idx + 2];
        }
        g_px[set][i] = x; g_py[set][i] = y; g_pz[set][i] = z;
    }
}

// ---------------- exact windowed KNN (one warp = 32 sorted queries) --------
__global__ __launch_bounds__(THREADS)
void knn_kernel()
{
    __shared__ __align__(16) float sx[WPB][CHW];
    __shared__ __align__(16) float sy[WPB][CHW];
    __shared__ __align__(16) float sz[WPB][CHW];

    const int tid  = threadIdx.x;
    const int lane = tid & 31;
    const int wib  = tid >> 5;
    const int gw   = blockIdx.x * WPB + wib;     // global warp id
    const int bd   = gw / WPD;                   // b*2 + dir
    const int wq   = gw % WPD;                   // warp's query-slice within set
    const int qset = bd;                         // queries = sorted set bd
    const int cset = bd ^ 1;                     // candidates = the other set
    const int slot = wq * QPW + lane;

    const float qx = g_px[qset][slot];
    const float qy = g_py[qset][slot];
    const float qz = g_pz[qset][slot];

    // warp query x-range (exact values)
    float xqmin = qx, xqmax = qx;
#pragma unroll
    for (int o = 16; o > 0; o >>= 1) {
        xqmin = fminf(xqmin, __shfl_xor_sync(0xffffffffu, xqmin, o));
        xqmax = fmaxf(xqmax, __shfl_xor_sync(0xffffffffu, xqmax, o));
    }

    const float* __restrict__ cx = g_px[cset];
    const float* __restrict__ cy = g_py[cset];
    const float* __restrict__ cz = g_pz[cset];

    float h[KNN];
#pragma unroll
    for (int i = 0; i < KNN; ++i) h[i] = 3.0e38f;
    unsigned tbits = __float_as_uint(3.0e38f);

    // scan one 128-candidate chunk (warp-cooperative smem tile)
    auto scan = [&](int c) {
        const int base = c * CHW;
        const float4 vx = reinterpret_cast<const float4*>(cx + base)[lane];
        const float4 vy = reinterpret_cast<const float4*>(cy + base)[lane];
        const float4 vz = reinterpret_cast<const float4*>(cz + base)[lane];
        __syncwarp();                             // tile free before overwrite
        reinterpret_cast<float4*>(sx[wib])[lane] = vx;
        reinterpret_cast<float4*>(sy[wib])[lane] = vy;
        reinterpret_cast<float4*>(sz[wib])[lane] = vz;
        __syncwarp();
#pragma unroll 4
        for (int j = 0; j < CHW; ++j) {
            const float dx = qx - sx[wib][j];     // broadcast LDS
            const float dy = qy - sy[wib][j];
            const float dz = qz - sz[wib][j];
            const float d2 = fmaf(dx, dx, fmaf(dy, dy, dz * dz));
            const unsigned db = __float_as_uint(d2);   // d2 >= 0: uint cmp == float cmp
            if (__builtin_expect(db < tbits, 0)) {
                float v = d2;
#pragma unroll
                for (int i = KNN - 1; i > 0; --i) {
                    const float hp = h[i - 1];
                    h[i] = fmaxf(hp, v);
                    v    = fminf(hp, v);
                }
                h[0] = v;
                tbits = __float_as_uint(h[KNN - 1]);
            }
        }
    };

    // rank-aligned start chunk, then symmetric expansion with exact bounds
    int c0 = (wq * QPW + QPW / 2) / CHW;
    if (c0 >= NCH) c0 = NCH - 1;
    scan(c0);
    int lo = c0, hi = c0 + 1;

    for (;;) {
        float tmax = h[KNN - 1];
#pragma unroll
        for (int o = 16; o > 0; o >>= 1)
            tmax = fmaxf(tmax, __shfl_xor_sync(0xffffffffu, tmax, o));
        const float td = sqrtf(tmax);

        // boundary reads are warp-uniform addresses -> uniform predicates
        const bool left  = (lo > 0)   && (cx[lo * CHW - 1] > xqmin - td - DELTA);
        const bool right = (hi < NCH) && (cx[hi * CHW]     < xqmax + td + DELTA);
        if (left)  { --lo; scan(lo); }
        if (right) { scan(hi); ++hi; }
        if (!left && !right) break;
    }

    // per-lane sum of 8 exact distances, warp-reduce, one partial per warp
    float s = 0.0f;
#pragma unroll
    for (int i = 0; i < KNN; ++i) s += sqrtf(h[i]);
#pragma unroll
    for (int o = 16; o > 0; o >>= 1)
        s += __shfl_down_sync(0xffffffffu, s, o);
    if (lane == 0) g_partials[gw] = s;
}

// ---------------- final deterministic reduction -----------------------------
__global__ __launch_bounds__(1024)
void reduce_kernel(float* __restrict__ out)
{
    const int t = threadIdx.x;
    float v = g_partials[t] + g_partials[t + 1024];
#pragma unroll
    for (int o = 16; o > 0; o >>= 1)
        v += __shfl_down_sync(0xffffffffu, v, o);

    __shared__ float ws[32];
    if ((t & 31) == 0) ws[t >> 5] = v;
    __syncthreads();
    if (t == 0) {
        float s = 0.0f;
#pragma unroll
        for (int i = 0; i < 32; ++i) s += ws[i];
        out[0] = s * (1.0f / (float)(B_ * N_ * KNN));
    }
}

extern "C" void kernel_launch(void* const* d_in, const int* in_sizes, int n_in,
                              void* d_out, int out_size)
{
    (void)in_sizes; (void)n_in; (void)out_size;
    const float* src  = (const float*)d_in[0];
    const float* tgt  = (const float*)d_in[1];
    const float* flow = (const float*)d_in[2];
    float* out = (float*)d_out;

    sortx_kernel<<<NSETS, 1024>>>(src, tgt, flow);
    knn_kernel<<<KBLOCKS, THREADS>>>();
    reduce_kernel<<<1, 1024>>>(out);
}

// round 12
// speedup vs baseline: 1.0020x; 1.0011x over previous
#include <cuda_runtime.h>
#include <math.h>

// ChamferLoss: B=4, N=8192, K=8 nearest neighbors, L2 norm.
// loss = mean over all (query, knn) exact distances, both directions.
//
// R10: EXACT windowed sweep. Sort each point set by x (bitonic on 19-bit
//      orderable-float keys, materialize sorted SoA). Each warp owns 32
//      consecutive x-sorted queries and expands a candidate window outward,
//      stopping when the boundary x is provably outside warp-max kth dist
//      (+ eps for key truncation). ~6-8x less pair work than brute force.

namespace {
constexpr int B_      = 4;
constexpr int N_      = 8192;
constexpr int KNN     = 8;
constexpr int NSETS   = B_ * 2;                 // b*2+s: s=0 pred(src+flow), s=1 tgt
constexpr int THREADS = 128;
constexpr int WPB     = THREADS / 32;           // 4 warps/block
constexpr int QPW     = 32;                     // queries per warp (1 per lane)
constexpr int WARPS_T = NSETS * N_ / QPW;       // 2048 warps total
constexpr int KBLOCKS = WARPS_T / WPB;          // 512 blocks
constexpr int WPD     = N_ / QPW;               // 256 warps per (batch,dir)
constexpr int CHW     = 128;                    // candidates per chunk
constexpr int NCH     = N_ / CHW;               // 64 chunks
constexpr float DELTA = 0.02f;                  // covers 19-bit key truncation (|x|<8)
}

// Scratch (static device globals: no allocation).
__device__ float g_px[NSETS][N_];               // sorted-by-x coordinates, SoA
__device__ float g_py[NSETS][N_];
__device__ float g_pz[NSETS][N_];
__device__ float g_partials[WARPS_T];

__device__ __forceinline__ unsigned ordf(float x) {  // monotone float->uint
    unsigned u = __float_as_uint(x);
    return (u & 0x80000000u) ? ~u : (u | 0x80000000u);
}

// ---------------- sort each set by x (one 1024-thread block per set) -------
__global__ __launch_bounds__(1024)
void sortx_kernel(const float* __restrict__ src,
                  const float* __restrict__ tgt,
                  const float* __restrict__ flow)
{
    __shared__ unsigned sk[N_];                  // 32 KB
    const int set = blockIdx.x;
    const int b   = set >> 1;
    const int s   = set & 1;
    const float* __restrict__ sb = src  + (size_t)b * N_ * 3;
    const float* __restrict__ tb = tgt  + (size_t)b * N_ * 3;
    const float* __restrict__ fb = flow + (size_t)b * N_ * 3;

    for (int i = threadIdx.x; i < N_; i += 1024) {
        const float x = (s == 0) ? (sb[3 * i] + fb[3 * i]) : tb[3 * i];
        sk[i] = (ordf(x) & 0xFFFFE000u) | (unsigned)i;   // 19-bit key | 13-bit idx
    }
    __syncthreads();

    for (int k = 2; k <= N_; k <<= 1) {
        for (int j = k >> 1; j > 0; j >>= 1) {
            for (int t = threadIdx.x; t < N_; t += 1024) {
                const int p = t ^ j;
                if (p > t) {
                    const unsigned a = sk[t], c = sk[p];
                    const bool up = ((t & k) == 0);
                    if ((a > c) == up) { sk[t] = c; sk[p] = a; }
                }
            }
            __syncthreads();
        }
    }

    for (int i = threadIdx.x; i < N_; i += 1024) {
        const int idx = (int)(sk[i] & (unsigned)(N_ - 1));
        float x, y, z;
        if (s == 0) {
            x = sb[3 * idx + 0] + fb[3 * idx + 0];
            y = sb[3 * idx + 1] + fb[3 * idx + 1];
            z = sb[3 * idx + 2] + fb[3 * idx + 2];
        } else {
            x = tb[3 * idx + 0]; y = tb[3 * idx + 1]; z = tb[3 * idx + 2];
        }
        g_px[set][i] = x; g_py[set][i] = y; g_pz[set][i] = z;
    }
}

// ---------------- exact windowed KNN (one warp = 32 sorted queries) --------
__global__ __launch_bounds__(THREADS)
void knn_kernel()
{
    __shared__ __align__(16) float sx[WPB][CHW];
    __shared__ __align__(16) float sy[WPB][CHW];
    __shared__ __align__(16) float sz[WPB][CHW];

    const int tid  = threadIdx.x;
    const int lane = tid & 31;
    const int wib  = tid >> 5;
    const int gw   = blockIdx.x * WPB + wib;     // global warp id
    const int bd   = gw / WPD;                   // b*2 + dir
    const int wq   = gw % WPD;                   // warp's query-slice within set
    const int qset = bd;                         // queries = sorted set bd
    const int cset = bd ^ 1;                     // candidates = the other set
    const int slot = wq * QPW + lane;

    const float qx = g_px[qset][slot];
    const float qy = g_py[qset][slot];
    const float qz = g_pz[qset][slot];

    // warp query x-range (exact values)
    float xqmin = qx, xqmax = qx;
#pragma unroll
    for (int o = 16; o > 0; o >>= 1) {
        xqmin = fminf(xqmin, __shfl_xor_sync(0xffffffffu, xqmin, o));
        xqmax = fmaxf(xqmax, __shfl_xor_sync(0xffffffffu, xqmax, o));
    }

    const float* __restrict__ cx = g_px[cset];
    const float* __restrict__ cy = g_py[cset];
    const float* __restrict__ cz = g_pz[cset];

    float h[KNN];
#pragma unroll
    for (int i = 0; i < KNN; ++i) h[i] = 3.0e38f;
    unsigned tbits = __float_as_uint(3.0e38f);

    // scan one 128-candidate chunk (warp-cooperative smem tile)
    auto scan = [&](int c) {
        const int base = c * CHW;
        const float4 vx = reinterpret_cast<const float4*>(cx + base)[lane];
        const float4 vy = reinterpret_cast<const float4*>(cy + base)[lane];
        const float4 vz = reinterpret_cast<const float4*>(cz + base)[lane];
        __syncwarp();                             // tile free before overwrite
        reinterpret_cast<float4*>(sx[wib])[lane] = vx;
        reinterpret_cast<float4*>(sy[wib])[lane] = vy;
        reinterpret_cast<float4*>(sz[wib])[lane] = vz;
        __syncwarp();
#pragma unroll 4
        for (int j = 0; j < CHW; ++j) {
            const float dx = qx - sx[wib][j];     // broadcast LDS
            const float dy = qy - sy[wib][j];
            const float dz = qz - sz[wib][j];
            const float d2 = fmaf(dx, dx, fmaf(dy, dy, dz * dz));
            const unsigned db = __float_as_uint(d2);   // d2 >= 0: uint cmp == float cmp
            if (__builtin_expect(db < tbits, 0)) {
                float v = d2;
#pragma unroll
                for (int i = KNN - 1; i > 0; --i) {
                    const float hp = h[i - 1];
                    h[i] = fmaxf(hp, v);
                    v    = fminf(hp, v);
                }
                h[0] = v;
                tbits = __float_as_uint(h[KNN - 1]);
            }
        }
    };

    // rank-aligned start chunk, then symmetric expansion with exact bounds
    int c0 = (wq * QPW + QPW / 2) / CHW;
    if (c0 >= NCH) c0 = NCH - 1;
    scan(c0);
    int lo = c0, hi = c0 + 1;

    for (;;) {
        float tmax = h[KNN - 1];
#pragma unroll
        for (int o = 16; o > 0; o >>= 1)
            tmax = fmaxf(tmax, __shfl_xor_sync(0xffffffffu, tmax, o));
        const float td = sqrtf(tmax);

        // boundary reads are warp-uniform addresses -> uniform predicates
        const bool left  = (lo > 0)   && (cx[lo * CHW - 1] > xqmin - td - DELTA);
        const bool right = (hi < NCH) && (cx[hi * CHW]     < xqmax + td + DELTA);
        if (left)  { --lo; scan(lo); }
        if (right) { scan(hi); ++hi; }
        if (!left && !right) break;
    }

    // per-lane sum of 8 exact distances, warp-reduce, one partial per warp
    float s = 0.0f;
#pragma unroll
    for (int i = 0; i < KNN; ++i) s += sqrtf(h[i]);
#pragma unroll
    for (int o = 16; o > 0; o >>= 1)
        s += __shfl_down_sync(0xffffffffu, s, o);
    if (lane == 0) g_partials[gw] = s;
}

// ---------------- final deterministic reduction -----------------------------
__global__ __launch_bounds__(1024)
void reduce_kernel(float* __restrict__ out)
{
    const int t = threadIdx.x;
    float v = g_partials[t] + g_partials[t + 1024];
#pragma unroll
    for (int o = 16; o > 0; o >>= 1)
        v += __shfl_down_sync(0xffffffffu, v, o);

    __shared__ float ws[32];
    if ((t & 31) == 0) ws[t >> 5] = v;
    __syncthreads();
    if (t == 0) {
        float s = 0.0f;
#pragma unroll
        for (int i = 0; i < 32; ++i) s += ws[i];
        out[0] = s * (1.0f / (float)(B_ * N_ * KNN));
    }
}

extern "C" void kernel_launch(void* const* d_in, const int* in_sizes, int n_in,
                              void* d_out, int out_size)
{
    (void)in_sizes; (void)n_in; (void)out_size;
    const float* src  = (const float*)d_in[0];
    const float* tgt  = (const float*)d_in[1];
    const float* flow = (const float*)d_in[2];
    float* out = (float*)d_out;

    sortx_kernel<<<NSETS, 1024>>>(src, tgt, flow);
    knn_kernel<<<KBLOCKS, THREADS>>>();
    reduce_kernel<<<1, 1024>>>(out);
}

// round 13
// speedup vs baseline: 1.2996x; 1.2970x over previous
#include <cuda_runtime.h>
#include <math.h>

// ChamferLoss: B=4, N=8192, K=8 nearest neighbors, L2 norm.
// loss = mean over all (query, knn) exact distances, both directions.
//
// R13: deterministic 256-bucket counting sort by x (~10us, analytic bucket
//      edges), then EXACT block-windowed scan: 128 consecutive bucket-sorted
//      queries per block, 1024-cand tiles, f32x2 over candidate pairs,
//      block-level termination using analytic bucket bounds.

namespace {
constexpr int   B_     = 4;
constexpr int   N_     = 8192;
constexpr int   KNN    = 8;
constexpr int   NSETS  = B_ * 2;             // b*2+s: s=0 pred(src+flow), s=1 tgt
constexpr int   NBUCK  = 256;
constexpr float BUCKW  = 0.0625f;            // 1/16 over [-8, 8)
constexpr int   TS     = 1024;               // candidates per tile
constexpr int   NCH    = N_ / TS;            // 8 tiles
constexpr int   KT     = 128;                // knn block threads = queries/block
constexpr int   KBLK   = NSETS * N_ / KT;    // 512 knn blocks
}

typedef unsigned long long ull;

__device__ __forceinline__ ull fx2_add(ull a, ull b) {
    ull r; asm("add.rn.f32x2 %0, %1, %2;" : "=l"(r) : "l"(a), "l"(b)); return r;
}
__device__ __forceinline__ ull fx2_mul(ull a, ull b) {
    ull r; asm("mul.rn.f32x2 %0, %1, %2;" : "=l"(r) : "l"(a), "l"(b)); return r;
}
__device__ __forceinline__ ull fx2_fma(ull a, ull b, ull c) {
    ull r; asm("fma.rn.f32x2 %0, %1, %2, %3;" : "=l"(r) : "l"(a), "l"(b), "l"(c)); return r;
}
__device__ __forceinline__ ull pack2(float lo, float hi) {
    return (ull)__float_as_uint(lo) | ((ull)__float_as_uint(hi) << 32);
}
__device__ __forceinline__ ull dupf(float v) {
    unsigned u = __float_as_uint(v);
    return (ull)u | ((ull)u << 32);
}
__device__ __forceinline__ int quant8(float x) {
    float q = (x + 8.0f) * 16.0f;
    q = fminf(fmaxf(q, 0.0f), 255.0f);
    return (int)q;
}

// Scratch (static device globals: no allocation).
__device__ float g_px[NSETS][N_];    // bucket-sorted coordinates, SoA
__device__ float g_py[NSETS][N_];
__device__ float g_pz[NSETS][N_];
__device__ float g_partials[KBLK];

// ---------- deterministic counting sort by x-bucket (1 block per set) ------
__global__ __launch_bounds__(1024)
void bucket_sort_kernel(const float* __restrict__ src,
                        const float* __restrict__ tgt,
                        const float* __restrict__ flow)
{
    __shared__ unsigned short wcnt[32][NBUCK];   // per-warp per-bucket (16 KB)
    __shared__ unsigned       bstart[NBUCK];
    __shared__ unsigned       tot[NBUCK];

    const int set = blockIdx.x;
    const int b   = set >> 1;
    const int s   = set & 1;
    const float* __restrict__ sb = src  + (size_t)b * N_ * 3;
    const float* __restrict__ tb = tgt  + (size_t)b * N_ * 3;
    const float* __restrict__ fb = flow + (size_t)b * N_ * 3;

    const int tid  = threadIdx.x;
    const int w    = tid >> 5;
    const int lane = tid & 31;
    const unsigned below = (1u << lane) - 1u;

    for (int i = tid; i < 32 * NBUCK; i += 1024)
        (&wcnt[0][0])[i] = 0;
    __syncthreads();

    // pass 1: count (leader-per-key non-atomic adds; order fixed)
    float xr[8];
#pragma unroll
    for (int it = 0; it < 8; ++it) {
        const int i = it * 1024 + tid;
        const float x = (s == 0) ? (sb[3 * i] + fb[3 * i]) : tb[3 * i];
        xr[it] = x;
        const int key = quant8(x);
        const unsigned mask = __match_any_sync(0xffffffffu, key);
        if ((mask & below) == 0u)   // leader lane for this key
            wcnt[w][key] = (unsigned short)(wcnt[w][key] + __popc(mask));
        __syncwarp();
    }
    __syncthreads();

    // per-bucket exclusive scan over warps (thread t owns bucket t)
    unsigned mytot = 0;
    if (tid < NBUCK) {
        unsigned run = 0;
        for (int ww = 0; ww < 32; ++ww) {
            const unsigned c = wcnt[ww][tid];
            wcnt[ww][tid] = (unsigned short)run;
            run += c;
        }
        tot[tid] = run; mytot = run;
    }
    __syncthreads();
    // inclusive scan of bucket totals
    for (int d = 1; d < NBUCK; d <<= 1) {
        unsigned v = 0;
        if (tid < NBUCK && tid >= d) v = tot[tid - d];
        __syncthreads();
        if (tid < NBUCK) tot[tid] += v;
        __syncthreads();
    }
    if (tid < NBUCK) bstart[tid] = tot[tid] - mytot;
    __syncthreads();

    // pass 2: deterministic scatter (per-warp cursors, lane-rank within key)
#pragma unroll
    for (int it = 0; it < 8; ++it) {
        const int i = it * 1024 + tid;
        const float x = xr[it];
        const int key = quant8(x);
        const unsigned mask = __match_any_sync(0xffffffffu, key);
        const unsigned r = __popc(mask & below);
        const unsigned basec = wcnt[w][key];
        __syncwarp();
        if (r == 0) wcnt[w][key] = (unsigned short)(basec + __popc(mask));
        __syncwarp();
        const unsigned pos = bstart[key] + basec + r;
        const float y = (s == 0) ? (sb[3 * i + 1] + fb[3 * i + 1]) : tb[3 * i + 1];
        const float z = (s == 0) ? (sb[3 * i + 2] + fb[3 * i + 2]) : tb[3 * i + 2];
        g_px[set][pos] = x; g_py[set][pos] = y; g_pz[set][pos] = z;
    }
}

// ---------- exact block-windowed KNN ---------------------------------------
__global__ __launch_bounds__(KT)
void knn_kernel()
{
    __shared__ __align__(16) ull sPX[TS / 2];    // negated candidate pairs
    __shared__ __align__(16) ull sPY[TS / 2];    // 12 KB total
    __shared__ __align__(16) ull sPZ[TS / 2];
    __shared__ float sred[KT / 32];
    __shared__ float sqmn[KT / 32], sqmx[KT / 32];

    const int tid  = threadIdx.x;
    const int lane = tid & 31;
    const int wib  = tid >> 5;
    const int qset  = blockIdx.x >> 6;           // 8 sets x 64 query chunks
    const int chunk = blockIdx.x & 63;
    const int cset  = qset ^ 1;
    const int slot  = chunk * KT + tid;          // this thread's query (sorted)

    const float qx = g_px[qset][slot];
    const float qy = g_py[qset][slot];
    const float qz = g_pz[qset][slot];
    const ull qx2 = dupf(qx), qy2 = dupf(qy), qz2 = dupf(qz);

    // block query x-range
    float mn = qx, mx = qx;
#pragma unroll
    for (int o = 16; o > 0; o >>= 1) {
        mn = fminf(mn, __shfl_xor_sync(0xffffffffu, mn, o));
        mx = fmaxf(mx, __shfl_xor_sync(0xffffffffu, mx, o));
    }
    if (lane == 0) { sqmn[wib] = mn; sqmx[wib] = mx; }
    __syncthreads();
    const float xqmin = fminf(fminf(sqmn[0], sqmn[1]), fminf(sqmn[2], sqmn[3]));
    const float xqmax = fmaxf(fmaxf(sqmx[0], sqmx[1]), fmaxf(sqmx[2], sqmx[3]));

    const float* __restrict__ cx = g_px[cset];
    const float* __restrict__ cy = g_py[cset];
    const float* __restrict__ cz = g_pz[cset];

    float h[KNN];
#pragma unroll
    for (int i = 0; i < KNN; ++i) h[i] = 3.0e38f;
    unsigned tbits = __float_as_uint(3.0e38f);

    auto scan_tile = [&](int c) {
        __syncthreads();                          // sred/tile consumed
        const int base = c * TS;
        for (int t = tid; t < TS / 4; t += KT) {  // 2 float4 per thread per coord
            const float4 vx = reinterpret_cast<const float4*>(cx + base)[t];
            const float4 vy = reinterpret_cast<const float4*>(cy + base)[t];
            const float4 vz = reinterpret_cast<const float4*>(cz + base)[t];
            sPX[2 * t]     = pack2(-vx.x, -vx.y);
            sPX[2 * t + 1] = pack2(-vx.z, -vx.w);
            sPY[2 * t]     = pack2(-vy.x, -vy.y);
            sPY[2 * t + 1] = pack2(-vy.z, -vy.w);
            sPZ[2 * t]     = pack2(-vz.x, -vz.y);
            sPZ[2 * t + 1] = pack2(-vz.z, -vz.w);
        }
        __syncthreads();
#pragma unroll 4
        for (int j = 0; j < TS / 2; ++j) {
            const ull dx = fx2_add(qx2, sPX[j]);  // broadcast LDS.64
            const ull dy = fx2_add(qy2, sPY[j]);
            const ull dz = fx2_add(qz2, sPZ[j]);
            const ull d2 = fx2_fma(dx, dx, fx2_fma(dy, dy, fx2_mul(dz, dz)));
            const unsigned d0 = (unsigned)d2;          // cand 2j
            const unsigned d1 = (unsigned)(d2 >> 32);  // cand 2j+1
            if (__builtin_expect(d0 < tbits, 0)) {
                float v = __uint_as_float(d0);
#pragma unroll
                for (int i = KNN - 1; i > 0; --i) {
                    const float hp = h[i - 1];
                    h[i] = fmaxf(hp, v);
                    v    = fminf(hp, v);
                }
                h[0] = v;
                tbits = __float_as_uint(h[KNN - 1]);
            }
            if (__builtin_expect(d1 < tbits, 0)) {
                float v = __uint_as_float(d1);
#pragma unroll
                for (int i = KNN - 1; i > 0; --i) {
                    const float hp = h[i - 1];
                    h[i] = fmaxf(hp, v);
                    v    = fminf(hp, v);
                }
                h[0] = v;
                tbits = __float_as_uint(h[KNN - 1]);
            }
        }
    };

    // start at the rank-aligned tile, expand outward with exact bucket bounds
    int c0 = chunk >> 3;                          // 64 chunks -> 8 tiles
    scan_tile(c0);
    int lo = c0, hi = c0 + 1;

    for (;;) {
        // block max of kth distances
        float t8 = h[KNN - 1];
#pragma unroll
        for (int o = 16; o > 0; o >>= 1)
            t8 = fmaxf(t8, __shfl_xor_sync(0xffffffffu, t8, o));
        if (lane == 0) sred[wib] = t8;
        __syncthreads();
        const float tmax = fmaxf(fmaxf(sred[0], sred[1]), fmaxf(sred[2], sred[3]));
        const float td = sqrtf(tmax);

        bool left = false, right = false;
        if (lo > 0) {
            const float xa = cx[lo * TS];         // uniform address
            const int ka = quant8(xa);
            const float bhi = (ka == 255) ? 3.0e38f : ((float)(ka + 1) * BUCKW - 8.0f);
            left = (bhi > xqmin - td);            // points left of window: x < bhi
        }
        if (hi < NCH) {
            const float xb = cx[hi * TS];
            const int kb = quant8(xb);
            const float blo = (kb == 0) ? -3.0e38f : ((float)kb * BUCKW - 8.0f);
            right = (blo < xqmax + td);           // points right of window: x >= blo
        }
        if (left)  { --lo; scan_tile(lo); }
        if (right) { scan_tile(hi); ++hi; }
        if (!left && !right) break;
    }

    // exact distance sum, deterministic block reduction
    float s = 0.0f;
#pragma unroll
    for (int i = 0; i < KNN; ++i) s += sqrtf(h[i]);
#pragma unroll
    for (int o = 16; o > 0; o >>= 1)
        s += __shfl_down_sync(0xffffffffu, s, o);
    __syncthreads();                              // sred free for reuse
    if (lane == 0) sred[wib] = s;
    __syncthreads();
    if (tid == 0)
        g_partials[blockIdx.x] = (sred[0] + sred[1]) + (sred[2] + sred[3]);
}

// ---------- final deterministic reduction ----------------------------------
__global__ __launch_bounds__(KBLK)
void reduce_kernel(float* __restrict__ out)
{
    const int t = threadIdx.x;
    float v = g_partials[t];
#pragma unroll
    for (int o = 16; o > 0; o >>= 1)
        v += __shfl_down_sync(0xffffffffu, v, o);

    __shared__ float ws[KBLK / 32];
    if ((t & 31) == 0) ws[t >> 5] = v;
    __syncthreads();
    if (t == 0) {
        float s = 0.0f;
#pragma unroll
        for (int i = 0; i < KBLK / 32; ++i) s += ws[i];
        out[0] = s * (1.0f / (float)(B_ * N_ * KNN));
    }
}

extern "C" void kernel_launch(void* const* d_in, const int* in_sizes, int n_in,
                              void* d_out, int out_size)
{
    (void)in_sizes; (void)n_in; (void)out_size;
    const float* src  = (const float*)d_in[0];
    const float* tgt  = (const float*)d_in[1];
    const float* flow = (const float*)d_in[2];
    float* out = (float*)d_out;

    bucket_sort_kernel<<<NSETS, 1024>>>(src, tgt, flow);
    knn_kernel<<<KBLK, KT>>>();
    reduce_kernel<<<1, KBLK>>>(out);
}

// round 14
// speedup vs baseline: 1.4870x; 1.1442x over previous
#include <cuda_runtime.h>
#include <math.h>

// ChamferLoss: B=4, N=8192, K=8 nearest neighbors, L2 norm.
// loss = mean over all (query, knn) exact distances, both directions.
//
// R14: bucket sort by x (analytic edges) -> EXACT windowed scan with
//      candidate-parity split: 2 blocks per 128-query chunk (4096 warps,
//      27.7/SM), each scans disjoint candidate-pair parity. Rank-aligned
//      tile first (threshold), ONE block reduce, fixed predicate loop over
//      remaining tiles. f32x2 candidate-pair math. Exact halver8 merge.

namespace {
constexpr int   B_     = 4;
constexpr int   N_     = 8192;
constexpr int   KNN    = 8;
constexpr int   NSETS  = B_ * 2;             // b*2+s: s=0 pred(src+flow), s=1 tgt
constexpr int   NBUCK  = 256;
constexpr float BUCKW  = 0.0625f;            // 1/16 over [-8, 8)
constexpr int   TS     = 1024;               // candidates per tile
constexpr int   NCH    = N_ / TS;            // 8 tiles
constexpr int   KT     = 128;                // knn threads = queries per chunk
constexpr int   QCH    = N_ / KT;            // 64 query chunks per set
constexpr int   KBLK   = NSETS * QCH * 2;    // 1024 knn blocks (x2 parity)
constexpr int   NQTOT  = NSETS * N_;         // 65536 query slots
constexpr int   MBLOCKS = NQTOT / 256;       // 256 merge blocks
}

typedef unsigned long long ull;

__device__ __forceinline__ ull fx2_add(ull a, ull b) {
    ull r; asm("add.rn.f32x2 %0, %1, %2;" : "=l"(r) : "l"(a), "l"(b)); return r;
}
__device__ __forceinline__ ull fx2_mul(ull a, ull b) {
    ull r; asm("mul.rn.f32x2 %0, %1, %2;" : "=l"(r) : "l"(a), "l"(b)); return r;
}
__device__ __forceinline__ ull fx2_fma(ull a, ull b, ull c) {
    ull r; asm("fma.rn.f32x2 %0, %1, %2, %3;" : "=l"(r) : "l"(a), "l"(b), "l"(c)); return r;
}
__device__ __forceinline__ ull pack2(float lo, float hi) {
    return (ull)__float_as_uint(lo) | ((ull)__float_as_uint(hi) << 32);
}
__device__ __forceinline__ ull dupf(float v) {
    unsigned u = __float_as_uint(v);
    return (ull)u | ((ull)u << 32);
}
__device__ __forceinline__ int quant8(float x) {
    float q = (x + 8.0f) * 16.0f;
    q = fminf(fmaxf(q, 0.0f), 255.0f);
    return (int)q;
}

// Scratch (static device globals: no allocation).
__device__ float g_px[NSETS][N_];    // bucket-sorted coordinates, SoA
__device__ float g_py[NSETS][N_];
__device__ float g_pz[NSETS][N_];
__device__ float g_knn[2][NQTOT][KNN];   // per-parity sorted partial d^2 lists
__device__ float g_partials[MBLOCKS];

// ---------- deterministic counting sort by x-bucket (1 block per set) ------
__global__ __launch_bounds__(1024)
void bucket_sort_kernel(const float* __restrict__ src,
                        const float* __restrict__ tgt,
                        const float* __restrict__ flow)
{
    __shared__ unsigned short wcnt[32][NBUCK];   // per-warp per-bucket (16 KB)
    __shared__ unsigned       bstart[NBUCK];
    __shared__ unsigned       tot[NBUCK];

    const int set = blockIdx.x;
    const int b   = set >> 1;
    const int s   = set & 1;
    const float* __restrict__ sb = src  + (size_t)b * N_ * 3;
    const float* __restrict__ tb = tgt  + (size_t)b * N_ * 3;
    const float* __restrict__ fb = flow + (size_t)b * N_ * 3;

    const int tid  = threadIdx.x;
    const int w    = tid >> 5;
    const int lane = tid & 31;
    const unsigned below = (1u << lane) - 1u;

    for (int i = tid; i < 32 * NBUCK; i += 1024)
        (&wcnt[0][0])[i] = 0;
    __syncthreads();

    // pass 1: count (leader-per-key non-atomic adds; order fixed)
    float xr[8];
#pragma unroll
    for (int it = 0; it < 8; ++it) {
        const int i = it * 1024 + tid;
        const float x = (s == 0) ? (sb[3 * i] + fb[3 * i]) : tb[3 * i];
        xr[it] = x;
        const int key = quant8(x);
        const unsigned mask = __match_any_sync(0xffffffffu, key);
        if ((mask & below) == 0u)   // leader lane for this key
            wcnt[w][key] = (unsigned short)(wcnt[w][key] + __popc(mask));
        __syncwarp();
    }
    __syncthreads();

    // per-bucket exclusive scan over warps (thread t owns bucket t)
    unsigned mytot = 0;
    if (tid < NBUCK) {
        unsigned run = 0;
        for (int ww = 0; ww < 32; ++ww) {
            const unsigned c = wcnt[ww][tid];
            wcnt[ww][tid] = (unsigned short)run;
            run += c;
        }
        tot[tid] = run; mytot = run;
    }
    __syncthreads();
    // inclusive scan of bucket totals
    for (int d = 1; d < NBUCK; d <<= 1) {
        unsigned v = 0;
        if (tid < NBUCK && tid >= d) v = tot[tid - d];
        __syncthreads();
        if (tid < NBUCK) tot[tid] += v;
        __syncthreads();
    }
    if (tid < NBUCK) bstart[tid] = tot[tid] - mytot;
    __syncthreads();

    // pass 2: deterministic scatter (per-warp cursors, lane-rank within key)
#pragma unroll
    for (int it = 0; it < 8; ++it) {
        const int i = it * 1024 + tid;
        const float x = xr[it];
        const int key = quant8(x);
        const unsigned mask = __match_any_sync(0xffffffffu, key);
        const unsigned r = __popc(mask & below);
        const unsigned basec = wcnt[w][key];
        __syncwarp();
        if (r == 0) wcnt[w][key] = (unsigned short)(basec + __popc(mask));
        __syncwarp();
        const unsigned pos = bstart[key] + basec + r;
        const float y = (s == 0) ? (sb[3 * i + 1] + fb[3 * i + 1]) : tb[3 * i + 1];
        const float z = (s == 0) ? (sb[3 * i + 2] + fb[3 * i + 2]) : tb[3 * i + 2];
        g_px[set][pos] = x; g_py[set][pos] = y; g_pz[set][pos] = z;
    }
}

// ---------- exact windowed KNN, candidate-parity split ---------------------
__global__ __launch_bounds__(KT)
void knn_kernel()
{
    __shared__ __align__(16) ull sPX[TS / 4];    // this parity's negated pairs
    __shared__ __align__(16) ull sPY[TS / 4];    // 6 KB total
    __shared__ __align__(16) ull sPZ[TS / 4];
    __shared__ float sred[KT / 32];
    __shared__ float sqmn[KT / 32], sqmx[KT / 32];
    __shared__ float sblo[NCH], sbhi[NCH];

    const int tid  = threadIdx.x;
    const int lane = tid & 31;
    const int wib  = tid >> 5;
    const int bi    = blockIdx.x;
    const int qset  = bi >> 7;                   // 8 sets
    const int rem   = bi & 127;
    const int chunk = rem >> 1;                  // 64 query chunks
    const int par   = rem & 1;                   // candidate-pair parity
    const int cset  = qset ^ 1;
    const int slot  = chunk * KT + tid;          // this thread's query (sorted)

    const float qx = g_px[qset][slot];
    const float qy = g_py[qset][slot];
    const float qz = g_pz[qset][slot];
    const ull qx2 = dupf(qx), qy2 = dupf(qy), qz2 = dupf(qz);

    // block query x-range
    float mn = qx, mx = qx;
#pragma unroll
    for (int o = 16; o > 0; o >>= 1) {
        mn = fminf(mn, __shfl_xor_sync(0xffffffffu, mn, o));
        mx = fmaxf(mx, __shfl_xor_sync(0xffffffffu, mx, o));
    }
    if (lane == 0) { sqmn[wib] = mn; sqmx[wib] = mx; }

    // analytic tile x-bounds (bucket-sorted: tile range within bucket edges)
    if (tid < NCH) {
        const int ka = quant8(g_px[cset][tid * TS]);
        const int kb = quant8(g_px[cset][tid * TS + TS - 1]);
        sblo[tid] = (ka == 0)   ? -3.0e38f : ((float)ka * BUCKW - 8.0f);
        sbhi[tid] = (kb == 255) ?  3.0e38f : ((float)(kb + 1) * BUCKW - 8.0f);
    }
    __syncthreads();
    const float xqmin = fminf(fminf(sqmn[0], sqmn[1]), fminf(sqmn[2], sqmn[3]));
    const float xqmax = fmaxf(fmaxf(sqmx[0], sqmx[1]), fmaxf(sqmx[2], sqmx[3]));

    const float* __restrict__ cx = g_px[cset];
    const float* __restrict__ cy = g_py[cset];
    const float* __restrict__ cz = g_pz[cset];
    const float2* __restrict__ cx2 = reinterpret_cast<const float2*>(cx);
    const float2* __restrict__ cy2 = reinterpret_cast<const float2*>(cy);
    const float2* __restrict__ cz2 = reinterpret_cast<const float2*>(cz);

    float h[KNN];
#pragma unroll
    for (int i = 0; i < KNN; ++i) h[i] = 3.0e38f;
    unsigned tbits = __float_as_uint(3.0e38f);

    auto scan_tile = [&](int c) {
        __syncthreads();                          // previous tile consumed
        const int pbase = (c * TS) / 2 + par;     // float2 index, parity offset
        for (int t = tid; t < TS / 4; t += KT) {
            const float2 vx = cx2[pbase + 2 * t]; // pair (2 cands) of this parity
            const float2 vy = cy2[pbase + 2 * t];
            const float2 vz = cz2[pbase + 2 * t];
            sPX[t] = pack2(-vx.x, -vx.y);
            sPY[t] = pack2(-vy.x, -vy.y);
            sPZ[t] = pack2(-vz.x, -vz.y);
        }
        __syncthreads();
#pragma unroll 4
        for (int j = 0; j < TS / 4; ++j) {
            const ull dx = fx2_add(qx2, sPX[j]);  // broadcast LDS.64
            const ull dy = fx2_add(qy2, sPY[j]);
            const ull dz = fx2_add(qz2, sPZ[j]);
            const ull d2 = fx2_fma(dx, dx, fx2_fma(dy, dy, fx2_mul(dz, dz)));
            const unsigned d0 = (unsigned)d2;
            const unsigned d1 = (unsigned)(d2 >> 32);
            if (__builtin_expect(d0 < tbits, 0)) {
                float v = __uint_as_float(d0);
#pragma unroll
                for (int i = KNN - 1; i > 0; --i) {
                    const float hp = h[i - 1];
                    h[i] = fmaxf(hp, v);
                    v    = fminf(hp, v);
                }
                h[0] = v;
                tbits = __float_as_uint(h[KNN - 1]);
            }
            if (__builtin_expect(d1 < tbits, 0)) {
                float v = __uint_as_float(d1);
#pragma unroll
                for (int i = KNN - 1; i > 0; --i) {
                    const float hp = h[i - 1];
                    h[i] = fmaxf(hp, v);
                    v    = fminf(hp, v);
                }
                h[0] = v;
                tbits = __float_as_uint(h[KNN - 1]);
            }
        }
    };

    // 1) rank-aligned tile -> per-query provable upper bound on true d8
    const int c0 = chunk >> 3;                    // 64 chunks -> 8 tiles
    scan_tile(c0);

    // 2) ONE block reduce of kth distances -> fixed window
    float t8 = h[KNN - 1];
#pragma unroll
    for (int o = 16; o > 0; o >>= 1)
        t8 = fmaxf(t8, __shfl_xor_sync(0xffffffffu, t8, o));
    if (lane == 0) sred[wib] = t8;
    __syncthreads();
    const float tmax = fmaxf(fmaxf(sred[0], sred[1]), fmaxf(sred[2], sred[3]));
    const float td = sqrtf(tmax);
    const float wlo = xqmin - td, whi = xqmax + td;

    // 3) fixed predicate loop over remaining tiles (block-uniform)
#pragma unroll
    for (int t = 0; t < NCH; ++t) {
        if (t == c0) continue;
        if (sbhi[t] > wlo && sblo[t] < whi) scan_tile(t);
    }

    // ---- write sorted partial list (d^2, ascending) ----
    float4* outp = reinterpret_cast<float4*>(&g_knn[par][qset * N_ + slot][0]);
    outp[0] = make_float4(h[0], h[1], h[2], h[3]);
    outp[1] = make_float4(h[4], h[5], h[6], h[7]);
}

// ---------- merge the two parity lists, sum sqrt, block-reduce -------------
__global__ __launch_bounds__(256)
void chamfer_merge_kernel()
{
    const int qg = blockIdx.x * 256 + threadIdx.x;
    const float4* pa = reinterpret_cast<const float4*>(&g_knn[0][qg][0]);
    const float4* pb = reinterpret_cast<const float4*>(&g_knn[1][qg][0]);
    const float4 a0 = pa[0], a1 = pa[1];
    const float4 b0 = pb[0], b1 = pb[1];

    // 8 smallest of two ascending 8-lists = {min(a[i], b[7-i])} (halver)
    float s = 0.0f;
    s += sqrtf(fminf(a0.x, b1.w));
    s += sqrtf(fminf(a0.y, b1.z));
    s += sqrtf(fminf(a0.z, b1.y));
    s += sqrtf(fminf(a0.w, b1.x));
    s += sqrtf(fminf(a1.x, b0.w));
    s += sqrtf(fminf(a1.y, b0.z));
    s += sqrtf(fminf(a1.z, b0.y));
    s += sqrtf(fminf(a1.w, b0.x));

#pragma unroll
    for (int o = 16; o > 0; o >>= 1)
        s += __shfl_down_sync(0xffffffffu, s, o);

    __shared__ float ws[8];
    if ((threadIdx.x & 31) == 0) ws[threadIdx.x >> 5] = s;
    __syncthreads();
    if (threadIdx.x == 0) {
        float t = 0.0f;
#pragma unroll
        for (int i = 0; i < 8; ++i) t += ws[i];
        g_partials[blockIdx.x] = t;
    }
}

// ---------- final deterministic reduction ----------------------------------
__global__ __launch_bounds__(MBLOCKS)
void reduce_kernel(float* __restrict__ out)
{
    const int t = threadIdx.x;
    float v = g_partials[t];
#pragma unroll
    for (int o = 16; o > 0; o >>= 1)
        v += __shfl_down_sync(0xffffffffu, v, o);

    __shared__ float ws[MBLOCKS / 32];
    if ((t & 31) == 0) ws[t >> 5] = v;
    __syncthreads();
    if (t == 0) {
        float s = 0.0f;
#pragma unroll
        for (int i = 0; i < MBLOCKS / 32; ++i) s += ws[i];
        out[0] = s * (1.0f / (float)(B_ * N_ * KNN));
    }
}

extern "C" void kernel_launch(void* const* d_in, const int* in_sizes, int n_in,
                              void* d_out, int out_size)
{
    (void)in_sizes; (void)n_in; (void)out_size;
    const float* src  = (const float*)d_in[0];
    const float* tgt  = (const float*)d_in[1];
    const float* flow = (const float*)d_in[2];
    float* out = (float*)d_out;

    bucket_sort_kernel<<<NSETS, 1024>>>(src, tgt, flow);
    knn_kernel<<<KBLK, KT>>>();
    chamfer_merge_kernel<<<MBLOCKS, 256>>>();
    reduce_kernel<<<1, MBLOCKS>>>(out);
}